// round 2
// baseline (speedup 1.0000x reference)
#include <cuda_runtime.h>
#include <cuda_bf16.h>

#define N_NODES 100000
#define N_EDGES 3200000
#define HID 16

// ---------------- device scratch (no allocations allowed) ----------------
__device__ __align__(16) float g_z[N_NODES * HID];      // relu(enc) output
__device__ __align__(16) float g_u[N_NODES * HID];      // z @ proc_w_rel
__device__ __align__(16) float g_agg16[N_NODES * HID];  // segment_sum(u)
__device__ float g_aggs[N_NODES];    // scalar agg, layer 1
__device__ float g_aggs2[N_NODES];   // scalar agg, layer 3
__device__ float g_s[N_NODES];       // z2 @ dec_w_rel  (scatter source, layer 3)
__device__ float g_r[N_NODES];       // z2 @ dec_w_root + dec_b (root term, layer 3)
__device__ int   g_src[N_EDGES];
__device__ int   g_dst[N_EDGES];
__device__ int   g_is64;

// ---------------- kernels ----------------

__global__ void k_init() {
    int i = blockIdx.x * blockDim.x + threadIdx.x;
    if (i < N_NODES * HID) g_agg16[i] = 0.f;
    if (i < N_NODES) { g_aggs[i] = 0.f; g_aggs2[i] = 0.f; }
}

// Detect whether edge_index is int64 or int32: node ids < 100000 < 2^32, so
// if the data is int64 every 8-byte word has a zero high half. If it is int32,
// the high half of an 8-byte word is a random edge value (zero w.p. 1e-5).
__global__ void k_detect(const void* ei) {
    const unsigned long long* p = (const unsigned long long*)ei;
    int bad = 0;
    for (int i = threadIdx.x; i < 256; i += blockDim.x)
        if ((p[i] >> 32) != 0ull) bad = 1;
    bad = __syncthreads_or(bad);
    if (threadIdx.x == 0) g_is64 = bad ? 0 : 1;
}

// Convert edge list to int32 arrays AND do the layer-1 scalar scatter.
__global__ void k_convert_scatter1(const void* ei, const float* __restrict__ x) {
    int e = blockIdx.x * blockDim.x + threadIdx.x;
    if (e >= N_EDGES) return;
    int s, d;
    if (g_is64) {
        const long long* p = (const long long*)ei;
        s = (int)p[e];
        d = (int)p[(long long)N_EDGES + e];
    } else {
        const int* p = (const int*)ei;
        s = p[e];
        d = p[N_EDGES + e];
    }
    g_src[e] = s;
    g_dst[e] = d;
    atomicAdd(&g_aggs[d], __ldg(&x[s]));
}

// Node pass 1: z = relu(aggs * enc_w_rel + x * enc_w_root + enc_b)  [N,16]
// and u = z @ proc_w_rel (precomputed so the edge pass scatters linearly).
__global__ void k_node1(const float* __restrict__ x,
                        const float* __restrict__ enc_w_rel,
                        const float* __restrict__ enc_w_root,
                        const float* __restrict__ enc_b,
                        const float* __restrict__ proc_w_rel) {
    __shared__ float sWrel[HID], sWroot[HID], sB[HID], sPW[HID * HID];
    int t = threadIdx.x;
    if (t < HID) { sWrel[t] = enc_w_rel[t]; sWroot[t] = enc_w_root[t]; sB[t] = enc_b[t]; }
    if (t < HID * HID) sPW[t] = proc_w_rel[t];
    __syncthreads();

    int i = blockIdx.x * blockDim.x + t;
    if (i >= N_NODES) return;

    float a  = g_aggs[i];
    float xv = __ldg(&x[i]);
    float z[HID];
#pragma unroll
    for (int f = 0; f < HID; f++)
        z[f] = fmaxf(fmaf(a, sWrel[f], fmaf(xv, sWroot[f], sB[f])), 0.f);

    float u[HID];
#pragma unroll
    for (int c = 0; c < HID; c++) u[c] = 0.f;
#pragma unroll
    for (int f = 0; f < HID; f++)
#pragma unroll
        for (int c = 0; c < HID; c++)
            u[c] = fmaf(z[f], sPW[f * HID + c], u[c]);

    float4* zp = (float4*)&g_z[i * HID];
    float4* up = (float4*)&g_u[i * HID];
#pragma unroll
    for (int q = 0; q < 4; q++) {
        zp[q] = make_float4(z[4 * q], z[4 * q + 1], z[4 * q + 2], z[4 * q + 3]);
        up[q] = make_float4(u[4 * q], u[4 * q + 1], u[4 * q + 2], u[4 * q + 3]);
    }
}

// Edge pass 2: agg16[dst] += u[src]  (16 floats), 4 lanes per edge, each lane
// one 16-byte vector reduction straight to L2.
__global__ void k_edge2() {
    long long t = (long long)blockIdx.x * blockDim.x + threadIdx.x;
    if (t >= (long long)4 * N_EDGES) return;
    int e = (int)(t >> 2);
    int c = (int)(t & 3);
    int s = g_src[e];
    int d = g_dst[e];
    const float4 v = *(const float4*)&g_u[s * HID + c * 4];
    float* p = &g_agg16[d * HID + c * 4];
    asm volatile("red.global.add.v4.f32 [%0], {%1, %2, %3, %4};"
                 :: "l"(p), "f"(v.x), "f"(v.y), "f"(v.z), "f"(v.w)
                 : "memory");
}

// Node pass 2: z2 = agg16 + proc_b + z @ proc_w_root, then fold the decoder:
//   s = z2 . dec_w_rel   (scatter source for layer 3, scalar!)
//   r = z2 . dec_w_root + dec_b
__global__ void k_node2(const float* __restrict__ proc_w_root,
                        const float* __restrict__ proc_b,
                        const float* __restrict__ dec_w_rel,
                        const float* __restrict__ dec_w_root,
                        const float* __restrict__ dec_b) {
    __shared__ float sPW[HID * HID], sB[HID], sDrel[HID], sDroot[HID];
    __shared__ float sDb;
    int t = threadIdx.x;
    if (t < HID) { sB[t] = proc_b[t]; sDrel[t] = dec_w_rel[t]; sDroot[t] = dec_w_root[t]; }
    if (t < HID * HID) sPW[t] = proc_w_root[t];
    if (t == 0) sDb = dec_b[0];
    __syncthreads();

    int i = blockIdx.x * blockDim.x + t;
    if (i >= N_NODES) return;

    float z[HID];
    const float4* zp = (const float4*)&g_z[i * HID];
#pragma unroll
    for (int q = 0; q < 4; q++) {
        float4 v = zp[q];
        z[4 * q] = v.x; z[4 * q + 1] = v.y; z[4 * q + 2] = v.z; z[4 * q + 3] = v.w;
    }

    float z2[HID];
    const float4* ap = (const float4*)&g_agg16[i * HID];
#pragma unroll
    for (int q = 0; q < 4; q++) {
        float4 v = ap[q];
        z2[4 * q] = v.x + sB[4 * q];
        z2[4 * q + 1] = v.y + sB[4 * q + 1];
        z2[4 * q + 2] = v.z + sB[4 * q + 2];
        z2[4 * q + 3] = v.w + sB[4 * q + 3];
    }
#pragma unroll
    for (int g = 0; g < HID; g++)
#pragma unroll
        for (int f = 0; f < HID; f++)
            z2[f] = fmaf(z[g], sPW[g * HID + f], z2[f]);

    float sv = 0.f, rv = sDb;
#pragma unroll
    for (int f = 0; f < HID; f++) {
        sv = fmaf(z2[f], sDrel[f], sv);
        rv = fmaf(z2[f], sDroot[f], rv);
    }
    g_s[i] = sv;
    g_r[i] = rv;
}

// Edge pass 3: aggs2[dst] += s[src]  (scalar scatter).
__global__ void k_edge3() {
    int e = blockIdx.x * blockDim.x + threadIdx.x;
    if (e >= N_EDGES) return;
    atomicAdd(&g_aggs2[g_dst[e]], g_s[g_src[e]]);
}

// Node pass 3: out = relu(aggs2 + r).
__global__ void k_node3(float* __restrict__ out) {
    int i = blockIdx.x * blockDim.x + threadIdx.x;
    if (i >= N_NODES) return;
    out[i] = fmaxf(g_aggs2[i] + g_r[i], 0.f);
}

// ---------------- launch ----------------
extern "C" void kernel_launch(void* const* d_in, const int* in_sizes, int n_in,
                              void* d_out, int out_size) {
    const float* x          = (const float*)d_in[0];
    const void*  ei         = d_in[1];
    const float* enc_w_rel  = (const float*)d_in[2];
    const float* enc_w_root = (const float*)d_in[3];
    const float* enc_b      = (const float*)d_in[4];
    const float* proc_w_rel = (const float*)d_in[5];
    const float* proc_w_root= (const float*)d_in[6];
    const float* proc_b     = (const float*)d_in[7];
    const float* dec_w_rel  = (const float*)d_in[8];
    const float* dec_w_root = (const float*)d_in[9];
    const float* dec_b      = (const float*)d_in[10];
    float* out = (float*)d_out;

    const int B = 256;
    k_init<<<(N_NODES * HID + B - 1) / B, B>>>();
    k_detect<<<1, 256>>>(ei);
    k_convert_scatter1<<<(N_EDGES + B - 1) / B, B>>>(ei, x);
    k_node1<<<(N_NODES + B - 1) / B, B>>>(x, enc_w_rel, enc_w_root, enc_b, proc_w_rel);
    k_edge2<<<(4LL * N_EDGES + B - 1) / B, B>>>();
    k_node2<<<(N_NODES + B - 1) / B, B>>>(proc_w_root, proc_b, dec_w_rel, dec_w_root, dec_b);
    k_edge3<<<(N_EDGES + B - 1) / B, B>>>();
    k_node3<<<(N_NODES + B - 1) / B, B>>>(out);
}

// round 3
// speedup vs baseline: 1.9292x; 1.9292x over previous
#include <cuda_runtime.h>
#include <cuda_bf16.h>

#define N_NODES 100000
#define N_EDGES 3200000
#define HID 16

// ---------------- device scratch ----------------
__device__ float  g_aggs[N_NODES];          // layer-1 scalar segment sum
__device__ __align__(8) float2 g_ag[N_NODES];   // per-node (alpha, gamma)
__device__ __align__(8) float2 g_AG[N_NODES];   // segment sums (A, G)
__device__ float  g_beta[N_NODES];          // z . (proc_w_root @ dec_w_rel)
__device__ float  g_dc[N_NODES];            // delta + c2 + dec_b
__device__ float  g_t[N_NODES];             // A + c1 + beta (scatter source)
__device__ float  g_T[N_NODES];             // final scalar segment sum
__device__ int    g_src[N_EDGES];
__device__ int    g_dst[N_EDGES];
__device__ int    g_is64;
// folded weights
__device__ float  g_w1[HID], g_w2[HID], g_w3[HID], g_w4[HID];
__device__ float  g_c1, g_c2;

// ---------------- kernels ----------------

__global__ void k_init() {
    int i = blockIdx.x * blockDim.x + threadIdx.x;
    if (i < N_NODES) {
        g_aggs[i] = 0.f;
        g_AG[i] = make_float2(0.f, 0.f);
        g_T[i] = 0.f;
    }
}

// int64 vs int32 edge_index detection (node ids < 1e5 << 2^32).
__global__ void k_detect(const void* ei) {
    const unsigned long long* p = (const unsigned long long*)ei;
    int bad = 0;
    for (int i = threadIdx.x; i < 256; i += blockDim.x)
        if ((p[i] >> 32) != 0ull) bad = 1;
    bad = __syncthreads_or(bad);
    if (threadIdx.x == 0) g_is64 = bad ? 0 : 1;
}

// Fold proc/dec weights:
//   w1 = proc_w_rel  @ dec_w_rel     w2 = proc_w_rel  @ dec_w_root
//   w3 = proc_w_root @ dec_w_rel     w4 = proc_w_root @ dec_w_root
//   c1 = proc_b . dec_w_rel          c2 = proc_b . dec_w_root
__global__ void k_foldw(const float* __restrict__ proc_w_rel,
                        const float* __restrict__ proc_w_root,
                        const float* __restrict__ proc_b,
                        const float* __restrict__ dec_w_rel,
                        const float* __restrict__ dec_w_root) {
    int t = threadIdx.x;            // 64 threads
    int g = t & 15;
    int which = t >> 4;
    const float* M = (which < 2) ? proc_w_rel : proc_w_root;
    const float* v = (which & 1) ? dec_w_root : dec_w_rel;
    float acc = 0.f;
#pragma unroll
    for (int f = 0; f < HID; f++) acc = fmaf(M[g * HID + f], v[f], acc);
    if (which == 0) g_w1[g] = acc;
    else if (which == 1) g_w2[g] = acc;
    else if (which == 2) g_w3[g] = acc;
    else g_w4[g] = acc;
    if (t == 0) {
        float a = 0.f, b = 0.f;
#pragma unroll
        for (int f = 0; f < HID; f++) {
            a = fmaf(proc_b[f], dec_w_rel[f], a);
            b = fmaf(proc_b[f], dec_w_root[f], b);
        }
        g_c1 = a; g_c2 = b;
    }
}

// Edge pass 1: convert edge list to int32 AND scatter x scalar.
__global__ void k_convert_scatter1(const void* ei, const float* __restrict__ x) {
    int e = blockIdx.x * blockDim.x + threadIdx.x;
    if (e >= N_EDGES) return;
    int s, d;
    if (g_is64) {
        const long long* p = (const long long*)ei;
        s = (int)p[e];
        d = (int)p[(long long)N_EDGES + e];
    } else {
        const int* p = (const int*)ei;
        s = p[e];
        d = p[N_EDGES + e];
    }
    g_src[e] = s;
    g_dst[e] = d;
    atomicAdd(&g_aggs[d], __ldg(&x[s]));
}

// Node pass 1: z = relu(enc), then project onto the four folded directions.
__global__ void k_node1(const float* __restrict__ x,
                        const float* __restrict__ enc_w_rel,
                        const float* __restrict__ enc_w_root,
                        const float* __restrict__ enc_b,
                        const float* __restrict__ dec_b) {
    __shared__ float sWrel[HID], sWroot[HID], sB[HID];
    __shared__ float s1[HID], s2[HID], s3[HID], s4[HID];
    __shared__ float sc2, sDb;
    int t = threadIdx.x;
    if (t < HID) {
        sWrel[t] = enc_w_rel[t]; sWroot[t] = enc_w_root[t]; sB[t] = enc_b[t];
        s1[t] = g_w1[t]; s2[t] = g_w2[t]; s3[t] = g_w3[t]; s4[t] = g_w4[t];
    }
    if (t == 0) { sc2 = g_c2; sDb = dec_b[0]; }
    __syncthreads();

    int i = blockIdx.x * blockDim.x + t;
    if (i >= N_NODES) return;

    float a  = g_aggs[i];
    float xv = __ldg(&x[i]);
    float al = 0.f, ga = 0.f, be = 0.f, de = 0.f;
#pragma unroll
    for (int f = 0; f < HID; f++) {
        float z = fmaxf(fmaf(a, sWrel[f], fmaf(xv, sWroot[f], sB[f])), 0.f);
        al = fmaf(z, s1[f], al);
        ga = fmaf(z, s2[f], ga);
        be = fmaf(z, s3[f], be);
        de = fmaf(z, s4[f], de);
    }
    g_ag[i] = make_float2(al, ga);
    g_beta[i] = be;
    g_dc[i] = de + sc2 + sDb;
}

// Edge pass 2: {A,G}[dst] += {alpha,gamma}[src]  (one v2 reduction per edge).
__global__ void k_edge2() {
    int e = blockIdx.x * blockDim.x + threadIdx.x;
    if (e >= N_EDGES) return;
    int s = g_src[e];
    int d = g_dst[e];
    float2 v = g_ag[s];
    float* p = (float*)&g_AG[d];
    asm volatile("red.global.add.v2.f32 [%0], {%1, %2};"
                 :: "l"(p), "f"(v.x), "f"(v.y) : "memory");
}

// Node pass 2: t = A + c1 + beta.
__global__ void k_node2() {
    int i = blockIdx.x * blockDim.x + threadIdx.x;
    if (i >= N_NODES) return;
    g_t[i] = g_AG[i].x + g_c1 + g_beta[i];
}

// Edge pass 3: T[dst] += t[src]  (scalar scatter).
__global__ void k_edge3() {
    int e = blockIdx.x * blockDim.x + threadIdx.x;
    if (e >= N_EDGES) return;
    atomicAdd(&g_T[g_dst[e]], g_t[g_src[e]]);
}

// Node pass 3: out = relu(T + G + dc).
__global__ void k_node3(float* __restrict__ out) {
    int i = blockIdx.x * blockDim.x + threadIdx.x;
    if (i >= N_NODES) return;
    out[i] = fmaxf(g_T[i] + g_AG[i].y + g_dc[i], 0.f);
}

// ---------------- launch ----------------
extern "C" void kernel_launch(void* const* d_in, const int* in_sizes, int n_in,
                              void* d_out, int out_size) {
    const float* x          = (const float*)d_in[0];
    const void*  ei         = d_in[1];
    const float* enc_w_rel  = (const float*)d_in[2];
    const float* enc_w_root = (const float*)d_in[3];
    const float* enc_b      = (const float*)d_in[4];
    const float* proc_w_rel = (const float*)d_in[5];
    const float* proc_w_root= (const float*)d_in[6];
    const float* proc_b     = (const float*)d_in[7];
    const float* dec_w_rel  = (const float*)d_in[8];
    const float* dec_w_root = (const float*)d_in[9];
    const float* dec_b      = (const float*)d_in[10];
    float* out = (float*)d_out;

    const int B = 256;
    const int GN = (N_NODES + B - 1) / B;
    const int GE = (N_EDGES + B - 1) / B;

    k_init<<<GN, B>>>();
    k_detect<<<1, 256>>>(ei);
    k_foldw<<<1, 64>>>(proc_w_rel, proc_w_root, proc_b, dec_w_rel, dec_w_root);
    k_convert_scatter1<<<GE, B>>>(ei, x);
    k_node1<<<GN, B>>>(x, enc_w_rel, enc_w_root, enc_b, dec_b);
    k_edge2<<<GE, B>>>();
    k_node2<<<GN, B>>>();
    k_edge3<<<GE, B>>>();
    k_node3<<<GN, B>>>(out);
}